// round 6
// baseline (speedup 1.0000x reference)
#include <cuda_runtime.h>

// BLIF: v[t] = exp(-exp(A_log[c])) * v[t-1] + x[t]
//       s[t] = (v[t] > 1)
//       out[0] = s[0]; out[t] = s[t] * (1 - s[t-1])   (pre-mask spikes)
//
// x: [T=256, B=8, C=128, H=14, W=14] f32, A_log: [128] f32, out: same shape.
// float4 lanes, 16-deep circular register pipeline with interleaved refill,
// 1-warp blocks for fine-grained SM balance.

#define T_LEN 256
#define PIX   200704          // B*C*H*W
#define P4    (PIX / 4)       // 50176 float4 lanes; H*W=196 % 4 == 0 -> one channel per lane
#define DEPTH 16              // pipeline depth (loads in flight per thread)

__device__ __forceinline__ void step(float4 xv, float4* __restrict__ op, int t, float d,
                                     float& vx, float& vy, float& vz, float& vw,
                                     float& px, float& py, float& pz, float& pw)
{
    vx = fmaf(d, vx, xv.x);
    vy = fmaf(d, vy, xv.y);
    vz = fmaf(d, vz, xv.z);
    vw = fmaf(d, vw, xv.w);

    float sx = (vx > 1.0f) ? 1.0f : 0.0f;
    float sy = (vy > 1.0f) ? 1.0f : 0.0f;
    float sz = (vz > 1.0f) ? 1.0f : 0.0f;
    float sw = (vw > 1.0f) ? 1.0f : 0.0f;

    float4 o;
    o.x = sx * (1.0f - px);
    o.y = sy * (1.0f - py);
    o.z = sz * (1.0f - pz);
    o.w = sw * (1.0f - pw);

    px = sx; py = sy; pz = sz; pw = sw;

    __stcs(op + t * P4, o);
}

__global__ __launch_bounds__(32, 1)
void blif_scan_kernel(const float* __restrict__ x,
                      const float* __restrict__ A_log,
                      float* __restrict__ out)
{
    int p4 = blockIdx.x * 32 + threadIdx.x;
    if (p4 >= P4) return;

    int c = (p4 / 49) & 127;   // 49 float4 lanes per (b,c) plane of 196 px

    double a = exp((double)A_log[c]);
    float d = (float)exp(-a);

    const float4* __restrict__ xp = reinterpret_cast<const float4*>(x) + p4;
    float4*       __restrict__ op = reinterpret_cast<float4*>(out) + p4;

    float vx = 0.f, vy = 0.f, vz = 0.f, vw = 0.f;
    float px = 0.f, py = 0.f, pz = 0.f, pw = 0.f;

    float4 buf[DEPTH];

    // prologue: fill the pipeline
    #pragma unroll
    for (int j = 0; j < DEPTH; j++)
        buf[j] = __ldcs(xp + j * P4);

    // steady state: consume one slot, immediately refill it DEPTH steps ahead,
    // then compute+store. Keeps ~DEPTH loads in flight at a steady issue rate.
    #pragma unroll 1
    for (int t0 = 0; t0 < T_LEN - DEPTH; t0 += DEPTH) {
        #pragma unroll
        for (int j = 0; j < DEPTH; j++) {
            float4 xv = buf[j];
            buf[j] = __ldcs(xp + (t0 + DEPTH + j) * P4);
            step(xv, op, t0 + j, d, vx, vy, vz, vw, px, py, pz, pw);
        }
    }

    // epilogue: drain the last DEPTH elements
    #pragma unroll
    for (int j = 0; j < DEPTH; j++)
        step(buf[j], op, T_LEN - DEPTH + j, d, vx, vy, vz, vw, px, py, pz, pw);
}

extern "C" void kernel_launch(void* const* d_in, const int* in_sizes, int n_in,
                              void* d_out, int out_size)
{
    const float* x     = (const float*)d_in[0];
    const float* A_log = (const float*)d_in[1];
    float*       out   = (float*)d_out;

    const int threads = 32;
    const int blocks  = (P4 + threads - 1) / threads;   // 1568 one-warp blocks
    blif_scan_kernel<<<blocks, threads>>>(x, A_log, out);
}

// round 7
// speedup vs baseline: 1.0627x; 1.0627x over previous
#include <cuda_runtime.h>

// BLIF: v[t] = exp(-exp(A_log[c])) * v[t-1] + x[t]
//       s[t] = (v[t] > 1)
//       out[0] = s[0]; out[t] = s[t] * (1 - s[t-1])   (pre-mask spikes)
//
// x: [T=256, B=8, C=128, H=14, W=14] f32, A_log: [128] f32, out: same shape.
// float4 lanes, 8-deep circular register pipeline with steady interleaved
// refill (one load issued per element consumed), 1-warp blocks for SM balance.

#define T_LEN 256
#define PIX   200704          // B*C*H*W
#define P4    (PIX / 4)       // 50176 float4 lanes; H*W=196 % 4 == 0 -> one channel per lane
#define DEPTH 8               // loads in flight per thread

__device__ __forceinline__ void step(float4 xv, float4* __restrict__ op, int t, float d,
                                     float& vx, float& vy, float& vz, float& vw,
                                     float& px, float& py, float& pz, float& pw)
{
    vx = fmaf(d, vx, xv.x);
    vy = fmaf(d, vy, xv.y);
    vz = fmaf(d, vz, xv.z);
    vw = fmaf(d, vw, xv.w);

    float sx = (vx > 1.0f) ? 1.0f : 0.0f;
    float sy = (vy > 1.0f) ? 1.0f : 0.0f;
    float sz = (vz > 1.0f) ? 1.0f : 0.0f;
    float sw = (vw > 1.0f) ? 1.0f : 0.0f;

    float4 o;
    o.x = sx * (1.0f - px);
    o.y = sy * (1.0f - py);
    o.z = sz * (1.0f - pz);
    o.w = sw * (1.0f - pw);

    px = sx; py = sy; pz = sz; pw = sw;

    __stcs(op + t * P4, o);
}

__global__ __launch_bounds__(32, 1)
void blif_scan_kernel(const float* __restrict__ x,
                      const float* __restrict__ A_log,
                      float* __restrict__ out)
{
    int p4 = blockIdx.x * 32 + threadIdx.x;
    if (p4 >= P4) return;

    int c = (p4 / 49) & 127;   // 49 float4 lanes per (b,c) plane of 196 px

    double a = exp((double)A_log[c]);
    float d = (float)exp(-a);

    const float4* __restrict__ xp = reinterpret_cast<const float4*>(x) + p4;
    float4*       __restrict__ op = reinterpret_cast<float4*>(out) + p4;

    float vx = 0.f, vy = 0.f, vz = 0.f, vw = 0.f;
    float px = 0.f, py = 0.f, pz = 0.f, pw = 0.f;

    float4 buf[DEPTH];

    // prologue: fill the pipeline
    #pragma unroll
    for (int j = 0; j < DEPTH; j++)
        buf[j] = __ldcs(xp + j * P4);

    // steady state: consume one slot, immediately reissue its load DEPTH steps
    // ahead, then compute+store. In-flight depth stays ~DEPTH with a smooth
    // 1-load-per-step issue rate (no bursts, no drain bubbles).
    #pragma unroll 1
    for (int t0 = 0; t0 < T_LEN - DEPTH; t0 += DEPTH) {
        #pragma unroll
        for (int j = 0; j < DEPTH; j++) {
            float4 xv = buf[j];
            buf[j] = __ldcs(xp + (t0 + DEPTH + j) * P4);
            step(xv, op, t0 + j, d, vx, vy, vz, vw, px, py, pz, pw);
        }
    }

    // epilogue: drain
    #pragma unroll
    for (int j = 0; j < DEPTH; j++)
        step(buf[j], op, T_LEN - DEPTH + j, d, vx, vy, vz, vw, px, py, pz, pw);
}

extern "C" void kernel_launch(void* const* d_in, const int* in_sizes, int n_in,
                              void* d_out, int out_size)
{
    const float* x     = (const float*)d_in[0];
    const float* A_log = (const float*)d_in[1];
    float*       out   = (float*)d_out;

    const int threads = 32;
    const int blocks  = (P4 + threads - 1) / threads;   // 1568 one-warp blocks
    blif_scan_kernel<<<blocks, threads>>>(x, A_log, out);
}